// round 1
// baseline (speedup 1.0000x reference)
#include <cuda_runtime.h>

#define BETA 0.95f
#define MB 512
#define N1 2048
#define N2 2048
#define N3 512
#define K1 1024
#define TSTEPS 16

// ---- scratch (static device globals; no allocation) ----
__device__ float g_c1[MB * N1];              // layer-1 currents (computed once)
__device__ float g_s1[TSTEPS * MB * N1];     // layer-1 spike trains, all 16 steps
__device__ float g_s2[MB * N2];              // layer-2 spikes, current step
__device__ float g_m2[MB * N2];              // layer-2 membrane
__device__ float g_m3[MB * N3];              // layer-3 membrane

// ---- init: zero membranes + output accumulator (graph-replay determinism) ----
__global__ void init_kernel(float* __restrict__ out) {
    int i = blockIdx.x * blockDim.x + threadIdx.x;
    if (i < MB * N2) g_m2[i] = 0.0f;
    if (i < MB * N3) { g_m3[i] = 0.0f; out[i] = 0.0f; }
}

// ---- layer-1: closed-form 16-step LIF recurrence on static current ----
__global__ void sim_layer1() {
    int i = blockIdx.x * blockDim.x + threadIdx.x;   // covers MB*N1
    float c = g_c1[i];
    float m = 0.0f;
#pragma unroll
    for (int t = 0; t < TSTEPS; t++) {
        m = BETA * m + c;
        float s = (m > 1.0f) ? 1.0f : 0.0f;
        m -= s;
        g_s1[t * (MB * N1) + i] = s;
    }
}

// ---- fused GEMM (+ optional LIF epilogue) ----
// Computes acc[m,n] = sum_k A[m,k] * W[n,k]   (A: [M,K] row-major, W: [N,K] row-major)
// MODE 0: out[m,n] = acc + bias[n]                       (layer-1 current)
// MODE 1: LIF update on mem, write spike to out          (layer 2)
// MODE 2: LIF update on mem, out[m,n] += spike           (layer 3, spike-count accumulate)
//
// Tiling: 64x64 CTA tile, BK=16, 256 threads, 4x4 register tile per thread.
template <int MODE>
__global__ void __launch_bounds__(256) gemm_snn(
    const float* __restrict__ A, const float* __restrict__ W,
    const float* __restrict__ bias, float* __restrict__ mem,
    float* __restrict__ out, int K, int N)
{
    __shared__ float As[16][64];
    __shared__ float Bs[16][64];

    const int tid = threadIdx.x;
    const int tx = tid & 15;        // 0..15 -> n direction (4 cols each)
    const int ty = tid >> 4;        // 0..15 -> m direction (4 rows each)
    const int n0 = blockIdx.x * 64;
    const int m0 = blockIdx.y * 64;

    // cooperative tile load mapping: each thread loads 1 float4 of A and 1 of W
    const int lrow = tid >> 2;      // 0..63
    const int lc4  = tid & 3;       // 0..3 (float4 column within 16-wide k-tile)

    const float4* __restrict__ Arow =
        reinterpret_cast<const float4*>(A + (size_t)(m0 + lrow) * K) + lc4;
    const float4* __restrict__ Wrow =
        reinterpret_cast<const float4*>(W + (size_t)(n0 + lrow) * K) + lc4;

    float acc[4][4] = {};

    const int nk = K >> 4;
    for (int kt = 0; kt < nk; kt++) {
        float4 av = Arow[kt * 4];
        float4 wv = Wrow[kt * 4];
        __syncthreads();   // previous iteration's smem reads complete
        As[lc4 * 4 + 0][lrow] = av.x;
        As[lc4 * 4 + 1][lrow] = av.y;
        As[lc4 * 4 + 2][lrow] = av.z;
        As[lc4 * 4 + 3][lrow] = av.w;
        Bs[lc4 * 4 + 0][lrow] = wv.x;
        Bs[lc4 * 4 + 1][lrow] = wv.y;
        Bs[lc4 * 4 + 2][lrow] = wv.z;
        Bs[lc4 * 4 + 3][lrow] = wv.w;
        __syncthreads();

#pragma unroll
        for (int k = 0; k < 16; k++) {
            float4 a = *reinterpret_cast<const float4*>(&As[k][ty * 4]);
            float4 b = *reinterpret_cast<const float4*>(&Bs[k][tx * 4]);
            acc[0][0] += a.x * b.x; acc[0][1] += a.x * b.y;
            acc[0][2] += a.x * b.z; acc[0][3] += a.x * b.w;
            acc[1][0] += a.y * b.x; acc[1][1] += a.y * b.y;
            acc[1][2] += a.y * b.z; acc[1][3] += a.y * b.w;
            acc[2][0] += a.z * b.x; acc[2][1] += a.z * b.y;
            acc[2][2] += a.z * b.z; acc[2][3] += a.z * b.w;
            acc[3][0] += a.w * b.x; acc[3][1] += a.w * b.y;
            acc[3][2] += a.w * b.z; acc[3][3] += a.w * b.w;
        }
    }

    // epilogue
#pragma unroll
    for (int i = 0; i < 4; i++) {
        const int m = m0 + ty * 4 + i;
#pragma unroll
        for (int j = 0; j < 4; j++) {
            const int n = n0 + tx * 4 + j;
            const size_t idx = (size_t)m * N + n;
            float v = acc[i][j] + bias[n];
            if (MODE == 0) {
                out[idx] = v;
            } else {
                float mm = BETA * mem[idx] + v;
                float s = (mm > 1.0f) ? 1.0f : 0.0f;
                mem[idx] = mm - s;
                if (MODE == 1) out[idx] = s;     // spike buffer
                else           out[idx] += s;    // spike-count accumulator
            }
        }
    }
}

extern "C" void kernel_launch(void* const* d_in, const int* in_sizes, int n_in,
                              void* d_out, int out_size)
{
    const float* x  = (const float*)d_in[0];
    const float* W1 = (const float*)d_in[1];
    const float* b1 = (const float*)d_in[2];
    const float* W2 = (const float*)d_in[3];
    const float* b2 = (const float*)d_in[4];
    const float* W3 = (const float*)d_in[5];
    const float* b3 = (const float*)d_in[6];
    float* out = (float*)d_out;

    float *c1p, *s1p, *s2p, *m2p, *m3p;
    cudaGetSymbolAddress((void**)&c1p, g_c1);
    cudaGetSymbolAddress((void**)&s1p, g_s1);
    cudaGetSymbolAddress((void**)&s2p, g_s2);
    cudaGetSymbolAddress((void**)&m2p, g_m2);
    cudaGetSymbolAddress((void**)&m3p, g_m3);

    // 1) zero membranes + output
    init_kernel<<<(MB * N2 + 255) / 256, 256>>>(out);

    // 2) layer-1 current, computed once: c1 = x @ W1^T + b1
    gemm_snn<0><<<dim3(N1 / 64, MB / 64), 256>>>(x, W1, b1, nullptr, c1p, K1, N1);

    // 3) full 16-step layer-1 spike trains (elementwise recurrence)
    sim_layer1<<<(MB * N1) / 256, 256>>>();

    // 4) 16 sequential steps through layers 2 and 3
    for (int t = 0; t < TSTEPS; t++) {
        gemm_snn<1><<<dim3(N2 / 64, MB / 64), 256>>>(
            s1p + (size_t)t * MB * N1, W2, b2, m2p, s2p, N1, N2);
        gemm_snn<2><<<dim3(N3 / 64, MB / 64), 256>>>(
            s2p, W3, b3, m3p, out, N2, N3);
    }
}

// round 8
// speedup vs baseline: 1.2767x; 1.2767x over previous
#include <cuda_runtime.h>
#include <cuda_bf16.h>
#include <cstdint>

#define BETA 0.95f
#define MB 512
#define L1N 2048
#define L2N 2048
#define L3N 512
#define K1IN 1024
#define TSTEPS 16

// ---------------- scratch (static device globals) ----------------
__device__ float g_c1[MB * L1N];              // layer-1 currents (computed once)
__device__ float g_s1[TSTEPS * MB * L1N];     // layer-1 spike trains (float, as in R1)
__device__ float g_s2[MB * L2N];              // layer-2 spikes, current step
__device__ float g_m2[MB * L2N];              // layer-2 membrane
__device__ float g_m3[MB * L3N];              // layer-3 membrane

// ---- init: zero membranes + output accumulator ----
__global__ void init_kernel(float* __restrict__ out) {
    int i = blockIdx.x * blockDim.x + threadIdx.x;
    if (i < MB * L2N) g_m2[i] = 0.0f;
    if (i < MB * L3N) { g_m3[i] = 0.0f; out[i] = 0.0f; }
}

// ---- layer-1: closed-form 16-step LIF recurrence on static current (verbatim R1) ----
__global__ void sim_layer1() {
    int i = blockIdx.x * blockDim.x + threadIdx.x;   // covers MB*L1N
    float c = g_c1[i];
    float m = 0.0f;
#pragma unroll
    for (int t = 0; t < TSTEPS; t++) {
        m = BETA * m + c;
        float s = (m > 1.0f) ? 1.0f : 0.0f;
        m -= s;
        g_s1[t * (MB * L1N) + i] = s;
    }
}

// ---------------- fp32 SIMT GEMM + fused LIF (bit-exact to R1's arithmetic) ----------------
// acc[m,n] = sum_k A[m,k] * W[n,k], ascending k, fp32 FFMA chain per output.
// MODE 0: out[m,n] = acc + bias[n]                       (layer-1 current)
// MODE 1: LIF update on mem, write spike (float) to out  (layer 2)
// MODE 2: LIF update on mem, out[m,n] += spike           (layer 3, accumulate)
//
// CTA tile TM x TN, 128 threads, per-thread WM x WN register tile. BK=16.
// Register-prefetch double buffering, one __syncthreads per k-iteration.
template <int MODE, int TM, int TN, int WM, int WN>
__global__ void __launch_bounds__(128) sgemm_snn(
    const float* __restrict__ A, const float* __restrict__ W,
    const float* __restrict__ bias, float* __restrict__ mem,
    float* __restrict__ out, int K, int nw)
{
    constexpr int TX = TN / WN;            // threads along n
    constexpr int TY = TM / WM;            // threads along m
    static_assert(TX * TY == 128, "128 threads");
    constexpr int ACH = TM * 16 / 4 / 128; // float4 A-chunks per thread per iter
    constexpr int BCH = TN * 16 / 4 / 128; // float4 B-chunks per thread per iter
    static_assert(ACH >= 1 && BCH >= 1, "tile sizes");

    __shared__ float As[2][16][TM];        // [buf][k][m]
    __shared__ float Bs[2][16][TN];        // [buf][k][n]

    const int tid = threadIdx.x;
    const int tx  = tid % TX;
    const int ty  = tid / TX;
    const int n0  = blockIdx.x * TN;
    const int m0  = blockIdx.y * TM;

    float acc[WM][WN];
#pragma unroll
    for (int i = 0; i < WM; i++)
#pragma unroll
        for (int j = 0; j < WN; j++) acc[i][j] = 0.0f;

    float4 pa[ACH], pb[BCH];
    const int niter = K >> 4;   // BK = 16

    // ---- prologue: fetch tile 0 into regs, store to buffer 0 ----
#pragma unroll
    for (int i = 0; i < ACH; i++) {
        int c = i * 128 + tid, row = c >> 2, kq = c & 3;
        pa[i] = *reinterpret_cast<const float4*>(A + (size_t)(m0 + row) * K + kq * 4);
    }
#pragma unroll
    for (int i = 0; i < BCH; i++) {
        int c = i * 128 + tid, row = c >> 2, kq = c & 3;
        pb[i] = *reinterpret_cast<const float4*>(W + (size_t)(n0 + row) * K + kq * 4);
    }
#pragma unroll
    for (int i = 0; i < ACH; i++) {
        int c = i * 128 + tid, row = c >> 2, kq = c & 3;
        As[0][kq * 4 + 0][row] = pa[i].x;
        As[0][kq * 4 + 1][row] = pa[i].y;
        As[0][kq * 4 + 2][row] = pa[i].z;
        As[0][kq * 4 + 3][row] = pa[i].w;
    }
#pragma unroll
    for (int i = 0; i < BCH; i++) {
        int c = i * 128 + tid, row = c >> 2, kq = c & 3;
        Bs[0][kq * 4 + 0][row] = pb[i].x;
        Bs[0][kq * 4 + 1][row] = pb[i].y;
        Bs[0][kq * 4 + 2][row] = pb[i].z;
        Bs[0][kq * 4 + 3][row] = pb[i].w;
    }

    for (int it = 0; it < niter; it++) {
        const int b = it & 1;
        __syncthreads();   // buffer b filled; prior readers of b^1 done

        const bool more = (it + 1 < niter);
        if (more) {
            const int k0 = (it + 1) * 16;
#pragma unroll
            for (int i = 0; i < ACH; i++) {
                int c = i * 128 + tid, row = c >> 2, kq = c & 3;
                pa[i] = *reinterpret_cast<const float4*>(A + (size_t)(m0 + row) * K + k0 + kq * 4);
            }
#pragma unroll
            for (int i = 0; i < BCH; i++) {
                int c = i * 128 + tid, row = c >> 2, kq = c & 3;
                pb[i] = *reinterpret_cast<const float4*>(W + (size_t)(n0 + row) * K + k0 + kq * 4);
            }
        }

        // ---- compute on buffer b; k ascending (bit-exact chain) ----
#pragma unroll
        for (int k = 0; k < 16; k++) {
            float a[WM], bb[WN];
#pragma unroll
            for (int q = 0; q < WM / 4; q++) {
                float4 v = *reinterpret_cast<const float4*>(&As[b][k][ty * WM + q * 4]);
                a[q * 4 + 0] = v.x; a[q * 4 + 1] = v.y; a[q * 4 + 2] = v.z; a[q * 4 + 3] = v.w;
            }
#pragma unroll
            for (int q = 0; q < WN / 4; q++) {
                float4 v = *reinterpret_cast<const float4*>(&Bs[b][k][tx * WN + q * 4]);
                bb[q * 4 + 0] = v.x; bb[q * 4 + 1] = v.y; bb[q * 4 + 2] = v.z; bb[q * 4 + 3] = v.w;
            }
#pragma unroll
            for (int i = 0; i < WM; i++)
#pragma unroll
                for (int j = 0; j < WN; j++)
                    acc[i][j] += a[i] * bb[j];
        }

        if (more) {
            const int nb = b ^ 1;
#pragma unroll
            for (int i = 0; i < ACH; i++) {
                int c = i * 128 + tid, row = c >> 2, kq = c & 3;
                As[nb][kq * 4 + 0][row] = pa[i].x;
                As[nb][kq * 4 + 1][row] = pa[i].y;
                As[nb][kq * 4 + 2][row] = pa[i].z;
                As[nb][kq * 4 + 3][row] = pa[i].w;
            }
#pragma unroll
            for (int i = 0; i < BCH; i++) {
                int c = i * 128 + tid, row = c >> 2, kq = c & 3;
                Bs[nb][kq * 4 + 0][row] = pb[i].x;
                Bs[nb][kq * 4 + 1][row] = pb[i].y;
                Bs[nb][kq * 4 + 2][row] = pb[i].z;
                Bs[nb][kq * 4 + 3][row] = pb[i].w;
            }
        }
    }

    // ---- epilogue (verbatim R1 expressions) ----
#pragma unroll
    for (int i = 0; i < WM; i++) {
        const int m = m0 + ty * WM + i;
#pragma unroll
        for (int j = 0; j < WN; j++) {
            const int n = n0 + tx * WN + j;
            const size_t idx = (size_t)m * nw + n;
            float v = acc[i][j] + bias[n];
            if (MODE == 0) {
                out[idx] = v;
            } else {
                float mm = BETA * mem[idx] + v;
                float s = (mm > 1.0f) ? 1.0f : 0.0f;
                mem[idx] = mm - s;
                if (MODE == 1) out[idx] = s;     // spike buffer
                else           out[idx] += s;    // spike-count accumulator
            }
        }
    }
}

// ---------------- host ----------------
extern "C" void kernel_launch(void* const* d_in, const int* in_sizes, int n_in,
                              void* d_out, int out_size)
{
    const float* x  = (const float*)d_in[0];
    const float* W1 = (const float*)d_in[1];
    const float* b1 = (const float*)d_in[2];
    const float* W2 = (const float*)d_in[3];
    const float* b2 = (const float*)d_in[4];
    const float* W3 = (const float*)d_in[5];
    const float* b3 = (const float*)d_in[6];
    float* out = (float*)d_out;

    float *c1p, *s1p, *s2p, *m2p, *m3p;
    cudaGetSymbolAddress((void**)&c1p, g_c1);
    cudaGetSymbolAddress((void**)&s1p, g_s1);
    cudaGetSymbolAddress((void**)&s2p, g_s2);
    cudaGetSymbolAddress((void**)&m2p, g_m2);
    cudaGetSymbolAddress((void**)&m3p, g_m3);

    // 1) zero membranes + output
    init_kernel<<<(MB * L2N + 255) / 256, 256>>>(out);

    // 2) layer-1 current, computed once: c1 = x @ W1^T + b1   (K=1024)
    //    128x64 tile, 8x8 per thread -> grid (2048/64, 512/128) = (32, 4) = 128 CTAs
    sgemm_snn<0, 128, 64, 8, 8><<<dim3(L1N / 64, MB / 128), 128>>>(
        x, W1, b1, nullptr, c1p, K1IN, L1N);

    // 3) full 16-step layer-1 spike trains (elementwise recurrence)
    sim_layer1<<<(MB * L1N) / 256, 256>>>();

    // 4) 16 sequential steps through layers 2 and 3
    for (int t = 0; t < TSTEPS; t++) {
        // layer 2: 512x2048, K=2048; 128x64 tile -> (32, 4) = 128 CTAs
        sgemm_snn<1, 128, 64, 8, 8><<<dim3(L2N / 64, MB / 128), 128>>>(
            s1p + (size_t)t * MB * L1N, W2, b2, m2p, s2p, L1N, L2N);
        // layer 3: 512x512, K=2048; 64x32 tile, 4x4 per thread -> (16, 8) = 128 CTAs
        sgemm_snn<2, 64, 32, 4, 4><<<dim3(L3N / 32, MB / 64), 128>>>(
            s2p, W3, b3, m3p, out, L2N, L3N);
    }
}

// round 9
// speedup vs baseline: 1.3797x; 1.0807x over previous
#include <cuda_runtime.h>
#include <cstdint>

#define BETA 0.95f
#define MB 512
#define L1N 2048
#define L2N 2048
#define L3N 512
#define K1IN 1024
#define TSTEPS 16

// ---------------- scratch (static device globals) ----------------
__device__ float g_c1[MB * L1N];              // layer-1 currents (computed once)
__device__ float g_s1[TSTEPS * MB * L1N];     // layer-1 spike trains
__device__ float g_s2[2][MB * L2N];           // layer-2 spikes, double-buffered
__device__ float g_m2[MB * L2N];              // layer-2 membrane
__device__ float g_m3[MB * L3N];              // layer-3 membrane

// ---- init: zero membranes + output accumulator ----
__global__ void init_kernel(float* __restrict__ out) {
    int i = blockIdx.x * blockDim.x + threadIdx.x;
    if (i < MB * L2N) g_m2[i] = 0.0f;
    if (i < MB * L3N) { g_m3[i] = 0.0f; out[i] = 0.0f; }
}

// ---- layer-1: closed-form 16-step LIF recurrence on static current ----
__global__ void sim_layer1() {
    int i = blockIdx.x * blockDim.x + threadIdx.x;   // covers MB*L1N
    float c = g_c1[i];
    float m = 0.0f;
#pragma unroll
    for (int t = 0; t < TSTEPS; t++) {
        m = BETA * m + c;
        float s = (m > 1.0f) ? 1.0f : 0.0f;
        m -= s;
        g_s1[t * (MB * L1N) + i] = s;
    }
}

// ---------------- 64x64-tile fp32 GEMM body + fused LIF (bit-exact chain) ----------------
// acc[m,n] = sum_k A[m,k] * W[n,k], ascending k, fp32 FFMA chain per output.
// 128 threads, per-thread 8x4 (ty=tid>>4 -> m, tx=tid&15 -> n). BK=16.
// MODE 0: out = acc + bias;  MODE 1: LIF, spike->out;  MODE 2: LIF, out += spike.
template <int MODE>
__device__ __forceinline__ void gemm64(
    float* __restrict__ As, float* __restrict__ Bs,   // each 2*16*64 floats
    int m0, int n0,
    const float* __restrict__ A, const float* __restrict__ W,
    const float* __restrict__ bias, float* __restrict__ mem,
    float* __restrict__ out, int K, int nw)
{
    const int tid = threadIdx.x;
    const int tx  = tid & 15;     // n: 4 cols each
    const int ty  = tid >> 4;     // m: 8 rows each

    // gmem->smem chunk mapping: c = i*128 + tid; row = c>>2 (0..63), kq = c&3
    const int rowa = tid >> 2;
    const int kq4  = (tid & 3) * 4;

    float acc[8][4];
#pragma unroll
    for (int i = 0; i < 8; i++)
#pragma unroll
        for (int j = 0; j < 4; j++) acc[i][j] = 0.0f;

    float4 pa[2], pb[2];
    const int niter = K >> 4;

    // prologue: tile 0 -> regs -> buffer 0
#pragma unroll
    for (int i = 0; i < 2; i++) {
        pa[i] = *reinterpret_cast<const float4*>(A + (size_t)(m0 + rowa + i * 32) * K + kq4);
        pb[i] = *reinterpret_cast<const float4*>(W + (size_t)(n0 + rowa + i * 32) * K + kq4);
    }
#pragma unroll
    for (int i = 0; i < 2; i++) {
        const int row = rowa + i * 32;
        As[(kq4 + 0) * 64 + row] = pa[i].x;
        As[(kq4 + 1) * 64 + row] = pa[i].y;
        As[(kq4 + 2) * 64 + row] = pa[i].z;
        As[(kq4 + 3) * 64 + row] = pa[i].w;
        Bs[(kq4 + 0) * 64 + row] = pb[i].x;
        Bs[(kq4 + 1) * 64 + row] = pb[i].y;
        Bs[(kq4 + 2) * 64 + row] = pb[i].z;
        Bs[(kq4 + 3) * 64 + row] = pb[i].w;
    }

    for (int it = 0; it < niter; it++) {
        const int b = it & 1;
        __syncthreads();   // buffer b filled; prior readers of b^1 done

        const bool more = (it + 1 < niter);
        if (more) {
            const int k0 = (it + 1) * 16;
#pragma unroll
            for (int i = 0; i < 2; i++) {
                pa[i] = *reinterpret_cast<const float4*>(A + (size_t)(m0 + rowa + i * 32) * K + k0 + kq4);
                pb[i] = *reinterpret_cast<const float4*>(W + (size_t)(n0 + rowa + i * 32) * K + k0 + kq4);
            }
        }

        // compute on buffer b; k ascending (bit-exact chain)
        float* Ab = As + b * (16 * 64);
        float* Bb = Bs + b * (16 * 64);
#pragma unroll
        for (int k = 0; k < 16; k++) {
            float a[8], bb[4];
            float4 v0 = *reinterpret_cast<const float4*>(Ab + k * 64 + ty * 8);
            float4 v1 = *reinterpret_cast<const float4*>(Ab + k * 64 + ty * 8 + 4);
            a[0] = v0.x; a[1] = v0.y; a[2] = v0.z; a[3] = v0.w;
            a[4] = v1.x; a[5] = v1.y; a[6] = v1.z; a[7] = v1.w;
            float4 w0 = *reinterpret_cast<const float4*>(Bb + k * 64 + tx * 4);
            bb[0] = w0.x; bb[1] = w0.y; bb[2] = w0.z; bb[3] = w0.w;
#pragma unroll
            for (int i = 0; i < 8; i++)
#pragma unroll
                for (int j = 0; j < 4; j++)
                    acc[i][j] += a[i] * bb[j];
        }

        if (more) {
            const int nb = b ^ 1;
            float* Ad = As + nb * (16 * 64);
            float* Bd = Bs + nb * (16 * 64);
#pragma unroll
            for (int i = 0; i < 2; i++) {
                const int row = rowa + i * 32;
                Ad[(kq4 + 0) * 64 + row] = pa[i].x;
                Ad[(kq4 + 1) * 64 + row] = pa[i].y;
                Ad[(kq4 + 2) * 64 + row] = pa[i].z;
                Ad[(kq4 + 3) * 64 + row] = pa[i].w;
                Bd[(kq4 + 0) * 64 + row] = pb[i].x;
                Bd[(kq4 + 1) * 64 + row] = pb[i].y;
                Bd[(kq4 + 2) * 64 + row] = pb[i].z;
                Bd[(kq4 + 3) * 64 + row] = pb[i].w;
            }
        }
    }

    // ---- epilogue (verbatim expressions; bit-exact) ----
#pragma unroll
    for (int i = 0; i < 8; i++) {
        const int m = m0 + ty * 8 + i;
#pragma unroll
        for (int j = 0; j < 4; j++) {
            const int n = n0 + tx * 4 + j;
            const size_t idx = (size_t)m * nw + n;
            float v = acc[i][j] + bias[n];
            if (MODE == 0) {
                out[idx] = v;
            } else {
                float mm = BETA * mem[idx] + v;
                float s = (mm > 1.0f) ? 1.0f : 0.0f;
                mem[idx] = mm - s;
                if (MODE == 1) out[idx] = s;     // spike buffer
                else           out[idx] += s;    // spike-count accumulator
            }
        }
    }
}

// single-GEMM wrapper
template <int MODE>
__global__ void __launch_bounds__(128) gemm64_kernel(
    const float* __restrict__ A, const float* __restrict__ W,
    const float* __restrict__ bias, float* __restrict__ mem,
    float* __restrict__ out, int K, int nw, int nbx)
{
    __shared__ float As[2 * 16 * 64];
    __shared__ float Bs[2 * 16 * 64];
    gemm64<MODE>(As, Bs, (blockIdx.x / nbx) * 64, (blockIdx.x % nbx) * 64,
                 A, W, bias, mem, out, K, nw);
}

// fused step: blocks [0,256) = layer-2 step t; blocks [256,320) = layer-3 step t-1
__global__ void __launch_bounds__(128) step_kernel(
    const float* __restrict__ s1t, const float* __restrict__ W2,
    const float* __restrict__ b2, float* __restrict__ m2, float* __restrict__ s2w,
    const float* __restrict__ s2r, const float* __restrict__ W3,
    const float* __restrict__ b3, float* __restrict__ m3, float* __restrict__ out)
{
    __shared__ float As[2 * 16 * 64];
    __shared__ float Bs[2 * 16 * 64];
    const int b = blockIdx.x;
    if (b < 256) {
        gemm64<1>(As, Bs, (b >> 5) * 64, (b & 31) * 64, s1t, W2, b2, m2, s2w, L1N, L2N);
    } else {
        const int c = b - 256;     // 64 blocks: 8 m-tiles x 8 n-tiles
        gemm64<2>(As, Bs, (c >> 3) * 64, (c & 7) * 64, s2r, W3, b3, m3, out, L2N, L3N);
    }
}

// ---------------- host ----------------
extern "C" void kernel_launch(void* const* d_in, const int* in_sizes, int n_in,
                              void* d_out, int out_size)
{
    const float* x  = (const float*)d_in[0];
    const float* W1 = (const float*)d_in[1];
    const float* b1 = (const float*)d_in[2];
    const float* W2 = (const float*)d_in[3];
    const float* b2 = (const float*)d_in[4];
    const float* W3 = (const float*)d_in[5];
    const float* b3 = (const float*)d_in[6];
    float* out = (float*)d_out;

    float *c1p, *s1p, *s2p, *m2p, *m3p;
    cudaGetSymbolAddress((void**)&c1p, g_c1);
    cudaGetSymbolAddress((void**)&s1p, g_s1);
    cudaGetSymbolAddress((void**)&s2p, g_s2);
    cudaGetSymbolAddress((void**)&m2p, g_m2);
    cudaGetSymbolAddress((void**)&m3p, g_m3);
    float* s2buf[2] = { s2p, s2p + (size_t)MB * L2N };

    // 1) zero membranes + output
    init_kernel<<<(MB * L2N + 255) / 256, 256>>>(out);

    // 2) layer-1 current, once: c1 = x @ W1^T + b1   (grid 8x32 = 256 CTAs)
    gemm64_kernel<0><<<256, 128>>>(x, W1, b1, nullptr, c1p, K1IN, L1N, 32);

    // 3) full 16-step layer-1 spike trains
    sim_layer1<<<(MB * L1N) / 256, 256>>>();

    // 4) layer-2 step 0 (grid 256)
    gemm64_kernel<1><<<256, 128>>>(s1p, W2, b2, m2p, s2buf[0], L1N, L2N, 32);

    // 5) fused steps: L2(t) || L3(t-1), t = 1..15 (grid 320)
    for (int t = 1; t < TSTEPS; t++) {
        step_kernel<<<320, 128>>>(
            s1p + (size_t)t * MB * L1N, W2, b2, m2p, s2buf[t & 1],
            s2buf[(t - 1) & 1], W3, b3, m3p, out);
    }

    // 6) trailing layer-3 step 15 (grid 64)
    gemm64_kernel<2><<<64, 128>>>(s2buf[1], W3, b3, m3p, out, L2N, L3N, 8);
}

// round 10
// speedup vs baseline: 1.4331x; 1.0387x over previous
#include <cuda_runtime.h>
#include <cstdint>

#define BETA 0.95f
#define MB 512
#define L1N 2048
#define L2N 2048
#define L3N 512
#define K1IN 1024
#define TSTEPS 16

// ---------------- scratch (static device globals) ----------------
__device__ float g_c1[MB * L1N];              // layer-1 currents (computed once)
__device__ float g_s1[TSTEPS * MB * L1N];     // layer-1 spike trains
__device__ float g_s2[2][MB * L2N];           // layer-2 spikes, double-buffered
__device__ float g_m2[MB * L2N];              // layer-2 membrane
__device__ float g_m3[MB * L3N];              // layer-3 membrane

// packed f32x2 helpers: per-lane IEEE fp32 fused multiply-add, RN -> bit-exact vs FFMA
#define FMA2(d, a, b) \
    asm("fma.rn.f32x2 %0, %1, %2, %0;" : "+l"(d) : "l"(a), "l"(b))
#define PACK2(d, x) \
    asm("mov.b64 %0, {%1, %1};" : "=l"(d) : "f"(x))
#define UNPACK2(lo, hi, v) \
    asm("mov.b64 {%0, %1}, %2;" : "=f"(lo), "=f"(hi) : "l"(v))

// ---- init: zero membranes + output accumulator ----
__global__ void init_kernel(float* __restrict__ out) {
    int i = blockIdx.x * blockDim.x + threadIdx.x;
    if (i < MB * L2N) g_m2[i] = 0.0f;
    if (i < MB * L3N) { g_m3[i] = 0.0f; out[i] = 0.0f; }
}

// ---- layer-1: closed-form 16-step LIF recurrence on static current ----
__global__ void sim_layer1() {
    int i = blockIdx.x * blockDim.x + threadIdx.x;   // covers MB*L1N
    float c = g_c1[i];
    float m = 0.0f;
#pragma unroll
    for (int t = 0; t < TSTEPS; t++) {
        m = BETA * m + c;
        float s = (m > 1.0f) ? 1.0f : 0.0f;
        m -= s;
        g_s1[t * (MB * L1N) + i] = s;
    }
}

// ---------------- 64x64-tile fp32 GEMM body + fused LIF (packed f32x2, bit-exact) ----------------
// acc[m,n] = sum_k A[m,k] * W[n,k], ascending k, per-element fused fp32 chain.
// 128 threads, per-thread 8x4 as 4 m-pairs x 4 n. BK=16.
// MODE 0: out = acc + bias;  MODE 1: LIF, spike->out;  MODE 2: LIF, out += spike.
template <int MODE>
__device__ __forceinline__ void gemm64(
    float* __restrict__ As, float* __restrict__ Bs,   // each 2*16*64 floats, 16B-aligned
    int m0, int n0,
    const float* __restrict__ A, const float* __restrict__ W,
    const float* __restrict__ bias, float* __restrict__ mem,
    float* __restrict__ out, int K, int nw)
{
    const int tid = threadIdx.x;
    const int tx  = tid & 15;     // n: 4 cols each
    const int ty  = tid >> 4;     // m: 8 rows each (4 packed pairs)

    // gmem->smem chunk mapping
    const int rowa = tid >> 2;
    const int kq4  = (tid & 3) * 4;

    uint64_t acc2[4][4];          // [m-pair][n]; 0ull == packed {0.0f, 0.0f}
#pragma unroll
    for (int i = 0; i < 4; i++)
#pragma unroll
        for (int j = 0; j < 4; j++) acc2[i][j] = 0ull;

    float4 pa[2], pb[2];
    const int niter = K >> 4;

    // prologue: tile 0 -> regs -> buffer 0
#pragma unroll
    for (int i = 0; i < 2; i++) {
        pa[i] = *reinterpret_cast<const float4*>(A + (size_t)(m0 + rowa + i * 32) * K + kq4);
        pb[i] = *reinterpret_cast<const float4*>(W + (size_t)(n0 + rowa + i * 32) * K + kq4);
    }
#pragma unroll
    for (int i = 0; i < 2; i++) {
        const int row = rowa + i * 32;
        As[(kq4 + 0) * 64 + row] = pa[i].x;
        As[(kq4 + 1) * 64 + row] = pa[i].y;
        As[(kq4 + 2) * 64 + row] = pa[i].z;
        As[(kq4 + 3) * 64 + row] = pa[i].w;
        Bs[(kq4 + 0) * 64 + row] = pb[i].x;
        Bs[(kq4 + 1) * 64 + row] = pb[i].y;
        Bs[(kq4 + 2) * 64 + row] = pb[i].z;
        Bs[(kq4 + 3) * 64 + row] = pb[i].w;
    }

    for (int it = 0; it < niter; it++) {
        const int b = it & 1;
        __syncthreads();   // buffer b filled; prior readers of b^1 done

        const bool more = (it + 1 < niter);
        if (more) {
            const int k0 = (it + 1) * 16;
#pragma unroll
            for (int i = 0; i < 2; i++) {
                pa[i] = *reinterpret_cast<const float4*>(A + (size_t)(m0 + rowa + i * 32) * K + k0 + kq4);
                pb[i] = *reinterpret_cast<const float4*>(W + (size_t)(n0 + rowa + i * 32) * K + k0 + kq4);
            }
        }

        // compute on buffer b; k ascending (per-element fused fp32 chain)
        float* Ab = As + b * (16 * 64);
        float* Bb = Bs + b * (16 * 64);
#pragma unroll
        for (int k = 0; k < 16; k++) {
            // A m-pairs, already packed in smem: rows (2i, 2i+1), lower lane = even row
            ulonglong2 a01 = *reinterpret_cast<const ulonglong2*>(Ab + k * 64 + ty * 8);
            ulonglong2 a23 = *reinterpret_cast<const ulonglong2*>(Ab + k * 64 + ty * 8 + 4);
            uint64_t ap[4] = { a01.x, a01.y, a23.x, a23.y };
            float4 w0 = *reinterpret_cast<const float4*>(Bb + k * 64 + tx * 4);
            uint64_t br[4];
            PACK2(br[0], w0.x);
            PACK2(br[1], w0.y);
            PACK2(br[2], w0.z);
            PACK2(br[3], w0.w);
#pragma unroll
            for (int i = 0; i < 4; i++)
#pragma unroll
                for (int j = 0; j < 4; j++)
                    FMA2(acc2[i][j], ap[i], br[j]);
        }

        if (more) {
            const int nb = b ^ 1;
            float* Ad = As + nb * (16 * 64);
            float* Bd = Bs + nb * (16 * 64);
#pragma unroll
            for (int i = 0; i < 2; i++) {
                const int row = rowa + i * 32;
                Ad[(kq4 + 0) * 64 + row] = pa[i].x;
                Ad[(kq4 + 1) * 64 + row] = pa[i].y;
                Ad[(kq4 + 2) * 64 + row] = pa[i].z;
                Ad[(kq4 + 3) * 64 + row] = pa[i].w;
                Bd[(kq4 + 0) * 64 + row] = pb[i].x;
                Bd[(kq4 + 1) * 64 + row] = pb[i].y;
                Bd[(kq4 + 2) * 64 + row] = pb[i].z;
                Bd[(kq4 + 3) * 64 + row] = pb[i].w;
            }
        }
    }

    // ---- epilogue (same per-element float expressions; bit-exact) ----
#pragma unroll
    for (int i = 0; i < 4; i++) {
#pragma unroll
        for (int j = 0; j < 4; j++) {
            float vlo, vhi;
            UNPACK2(vlo, vhi, acc2[i][j]);
            const int n = n0 + tx * 4 + j;
#pragma unroll
            for (int h = 0; h < 2; h++) {
                const int m = m0 + ty * 8 + i * 2 + h;
                const size_t idx = (size_t)m * nw + n;
                float v = (h ? vhi : vlo) + bias[n];
                if (MODE == 0) {
                    out[idx] = v;
                } else {
                    float mm = BETA * mem[idx] + v;
                    float s = (mm > 1.0f) ? 1.0f : 0.0f;
                    mem[idx] = mm - s;
                    if (MODE == 1) out[idx] = s;     // spike buffer
                    else           out[idx] += s;    // spike-count accumulator
                }
            }
        }
    }
}

// single-GEMM wrapper
template <int MODE>
__global__ void __launch_bounds__(128) gemm64_kernel(
    const float* __restrict__ A, const float* __restrict__ W,
    const float* __restrict__ bias, float* __restrict__ mem,
    float* __restrict__ out, int K, int nw, int nbx)
{
    __shared__ __align__(16) float As[2 * 16 * 64];
    __shared__ __align__(16) float Bs[2 * 16 * 64];
    gemm64<MODE>(As, Bs, (blockIdx.x / nbx) * 64, (blockIdx.x % nbx) * 64,
                 A, W, bias, mem, out, K, nw);
}

// fused step: blocks [0,256) = layer-2 step t; blocks [256,320) = layer-3 step t-1
__global__ void __launch_bounds__(128) step_kernel(
    const float* __restrict__ s1t, const float* __restrict__ W2,
    const float* __restrict__ b2, float* __restrict__ m2, float* __restrict__ s2w,
    const float* __restrict__ s2r, const float* __restrict__ W3,
    const float* __restrict__ b3, float* __restrict__ m3, float* __restrict__ out)
{
    __shared__ __align__(16) float As[2 * 16 * 64];
    __shared__ __align__(16) float Bs[2 * 16 * 64];
    const int b = blockIdx.x;
    if (b < 256) {
        gemm64<1>(As, Bs, (b >> 5) * 64, (b & 31) * 64, s1t, W2, b2, m2, s2w, L1N, L2N);
    } else {
        const int c = b - 256;     // 64 blocks: 8 m-tiles x 8 n-tiles
        gemm64<2>(As, Bs, (c >> 3) * 64, (c & 7) * 64, s2r, W3, b3, m3, out, L2N, L3N);
    }
}

// ---------------- host ----------------
extern "C" void kernel_launch(void* const* d_in, const int* in_sizes, int n_in,
                              void* d_out, int out_size)
{
    const float* x  = (const float*)d_in[0];
    const float* W1 = (const float*)d_in[1];
    const float* b1 = (const float*)d_in[2];
    const float* W2 = (const float*)d_in[3];
    const float* b2 = (const float*)d_in[4];
    const float* W3 = (const float*)d_in[5];
    const float* b3 = (const float*)d_in[6];
    float* out = (float*)d_out;

    float *c1p, *s1p, *s2p, *m2p, *m3p;
    cudaGetSymbolAddress((void**)&c1p, g_c1);
    cudaGetSymbolAddress((void**)&s1p, g_s1);
    cudaGetSymbolAddress((void**)&s2p, g_s2);
    cudaGetSymbolAddress((void**)&m2p, g_m2);
    cudaGetSymbolAddress((void**)&m3p, g_m3);
    float* s2buf[2] = { s2p, s2p + (size_t)MB * L2N };

    // 1) zero membranes + output
    init_kernel<<<(MB * L2N + 255) / 256, 256>>>(out);

    // 2) layer-1 current, once: c1 = x @ W1^T + b1   (grid 8x32 = 256 CTAs)
    gemm64_kernel<0><<<256, 128>>>(x, W1, b1, nullptr, c1p, K1IN, L1N, 32);

    // 3) full 16-step layer-1 spike trains
    sim_layer1<<<(MB * L1N) / 256, 256>>>();

    // 4) layer-2 step 0 (grid 256)
    gemm64_kernel<1><<<256, 128>>>(s1p, W2, b2, m2p, s2buf[0], L1N, L2N, 32);

    // 5) fused steps: L2(t) || L3(t-1), t = 1..15 (grid 320)
    for (int t = 1; t < TSTEPS; t++) {
        step_kernel<<<320, 128>>>(
            s1p + (size_t)t * MB * L1N, W2, b2, m2p, s2buf[t & 1],
            s2buf[(t - 1) & 1], W3, b3, m3p, out);
    }

    // 6) trailing layer-3 step 15 (grid 64)
    gemm64_kernel<2><<<64, 128>>>(s2buf[1], W3, b3, m3p, out, L2N, L3N, 8);
}

// round 11
// speedup vs baseline: 1.5452x; 1.0782x over previous
#include <cuda_runtime.h>
#include <cstdint>

#define BETA 0.95f
#define MB 512
#define L1N 2048
#define L2N 2048
#define L3N 512
#define K1IN 1024
#define TSTEPS 16

// ---------------- scratch (static device globals; transposed layouts) ----------------
__device__ float g_xT [K1IN * MB];             // xT [k][m]
__device__ float g_w1T[K1IN * L1N];            // W1T[k][n]
__device__ float g_w2T[L1N * L2N];             // W2T[k][n]
__device__ float g_w3T[L2N * L3N];             // W3T[k][n]
__device__ float g_c1T[L1N * MB];              // c1T[n1][m]
__device__ float g_s1T[TSTEPS][L1N * MB];      // s1T[t][k][m]
__device__ float g_s2T[2][L2N * MB];           // s2T double-buffered [k][m]
__device__ float g_m2T[L2N * MB];              // membranes, n-major
__device__ float g_m3T[L3N * MB];

// packed f32x2: per-lane IEEE fp32 FMA (RN) -> bit-exact vs FFMA
#define FMA2(d, a, b) \
    asm("fma.rn.f32x2 %0, %1, %2, %0;" : "+l"(d) : "l"(a), "l"(b))
#define PACK2(d, x) \
    asm("mov.b64 %0, {%1, %1};" : "=l"(d) : "f"(x))
#define UNPACK2(lo, hi, v) \
    asm("mov.b64 {%0, %1}, %2;" : "=f"(lo), "=f"(hi) : "l"(v))

// ---------------- transpose: src[R][C] -> dst[C][R], coalesced both sides ----------------
__global__ void transpose_k(const float* __restrict__ src, float* __restrict__ dst,
                            int R, int C) {
    __shared__ float t[32][33];
    const int c0 = blockIdx.x * 32, r0 = blockIdx.y * 32;
    for (int j = threadIdx.y; j < 32; j += 8)
        t[j][threadIdx.x] = src[(size_t)(r0 + j) * C + c0 + threadIdx.x];
    __syncthreads();
    for (int j = threadIdx.y; j < 32; j += 8)
        dst[(size_t)(c0 + j) * R + r0 + threadIdx.x] = t[threadIdx.x][j];
}

// ---- init: zero membranes + output accumulator ----
__global__ void init_kernel(float* __restrict__ out) {
    int i = blockIdx.x * blockDim.x + threadIdx.x;
    if (i < MB * L2N) g_m2T[i] = 0.0f;
    if (i < MB * L3N) { g_m3T[i] = 0.0f; out[i] = 0.0f; }
}

// ---- layer-1: closed-form 16-step LIF on static current; fully coalesced ----
__global__ void sim_layer1() {
    int i = blockIdx.x * blockDim.x + threadIdx.x;   // linear over c1T [n][m]
    float c = g_c1T[i];
    float m = 0.0f;
#pragma unroll
    for (int t = 0; t < TSTEPS; t++) {
        m = BETA * m + c;
        float s = (m > 1.0f) ? 1.0f : 0.0f;
        m -= s;
        g_s1T[t][i] = s;
    }
}

// ---------------- transposed-operand fp32x2 GEMM + fused LIF (bit-exact chain) ----------------
// C[m,n] = sum_k AT[k,m] * BT[k,n], ascending k, per-element fused fp32 chain.
// Tile 64m x 64n, 256 threads, per-thread 4m(2 pairs) x 4n. BK=32, double-buffered.
// MODE 0: c1T[n*MB+m] = acc + bias[n]
// MODE 1: LIF on mem[n*MB+m], spike -> outp[n*MB+m]        (s2T)
// MODE 2: LIF on mem[n*MB+m], outp[m*Ntot+n] += spike      (final out, row-major)
template <int MODE>
__device__ __forceinline__ void gemmT(
    float* __restrict__ As, float* __restrict__ Bs,   // each 2*32*64 floats, 16B-aligned
    int m0, int n0,
    const float* __restrict__ AT, const float* __restrict__ BT,
    const float* __restrict__ bias, float* __restrict__ mem,
    float* __restrict__ outp, int K, int Ntot)
{
    const int tid = threadIdx.x;
    const int tx  = tid & 15;       // n: 4 cols
    const int ty  = tid >> 4;       // m: 4 rows (2 packed pairs)

    // tile-load mapping: chunk q = i*256 + tid -> kk = q>>4 (0..31), mq = (q&15)*4
    const int kkb = tid >> 4;       // + i*16
    const int mq  = (tid & 15) * 4;

    uint64_t acc2[2][4];
#pragma unroll
    for (int i = 0; i < 2; i++)
#pragma unroll
        for (int j = 0; j < 4; j++) acc2[i][j] = 0ull;

    float4 pa[2], pb[2];
    const int niter = K >> 5;       // BK = 32

    // prologue: tile 0 -> regs -> buffer 0 (coalesced LDG.128, conflict-free STS.128)
#pragma unroll
    for (int i = 0; i < 2; i++) {
        const int kk = i * 16 + kkb;
        pa[i] = *reinterpret_cast<const float4*>(AT + (size_t)kk * MB   + m0 + mq);
        pb[i] = *reinterpret_cast<const float4*>(BT + (size_t)kk * Ntot + n0 + mq);
    }
#pragma unroll
    for (int i = 0; i < 2; i++) {
        const int kk = i * 16 + kkb;
        *reinterpret_cast<float4*>(As + kk * 64 + mq) = pa[i];
        *reinterpret_cast<float4*>(Bs + kk * 64 + mq) = pb[i];
    }

    for (int it = 0; it < niter; it++) {
        const int b = it & 1;
        __syncthreads();   // buffer b filled; prior readers of b^1 done

        const bool more = (it + 1 < niter);
        if (more) {
            const int k0 = (it + 1) * 32;
#pragma unroll
            for (int i = 0; i < 2; i++) {
                const int kk = k0 + i * 16 + kkb;
                pa[i] = *reinterpret_cast<const float4*>(AT + (size_t)kk * MB   + m0 + mq);
                pb[i] = *reinterpret_cast<const float4*>(BT + (size_t)kk * Ntot + n0 + mq);
            }
        }

        // compute on buffer b; k ascending (bit-exact per-element chain)
        float* Ab = As + b * (32 * 64);
        float* Bb = Bs + b * (32 * 64);
#pragma unroll
        for (int k = 0; k < 32; k++) {
            // A already m-pair packed in smem: rows (ty*4+0,1) and (ty*4+2,3)
            ulonglong2 ap2 = *reinterpret_cast<const ulonglong2*>(Ab + k * 64 + ty * 4);
            float4 w = *reinterpret_cast<const float4*>(Bb + k * 64 + tx * 4);
            uint64_t br0, br1, br2, br3;
            PACK2(br0, w.x);
            PACK2(br1, w.y);
            PACK2(br2, w.z);
            PACK2(br3, w.w);
            FMA2(acc2[0][0], ap2.x, br0);
            FMA2(acc2[0][1], ap2.x, br1);
            FMA2(acc2[0][2], ap2.x, br2);
            FMA2(acc2[0][3], ap2.x, br3);
            FMA2(acc2[1][0], ap2.y, br0);
            FMA2(acc2[1][1], ap2.y, br1);
            FMA2(acc2[1][2], ap2.y, br2);
            FMA2(acc2[1][3], ap2.y, br3);
        }

        if (more) {
            const int nb = b ^ 1;
            float* Ad = As + nb * (32 * 64);
            float* Bd = Bs + nb * (32 * 64);
#pragma unroll
            for (int i = 0; i < 2; i++) {
                const int kk = i * 16 + kkb;
                *reinterpret_cast<float4*>(Ad + kk * 64 + mq) = pa[i];
                *reinterpret_cast<float4*>(Bd + kk * 64 + mq) = pb[i];
            }
        }
    }

    // ---- epilogue (identical per-element float expressions; bit-exact) ----
#pragma unroll
    for (int j = 0; j < 4; j++) {
        const int n = n0 + tx * 4 + j;
        const float bj = bias[n];
        float v[4];
        UNPACK2(v[0], v[1], acc2[0][j]);   // m = ty*4+0, +1
        UNPACK2(v[2], v[3], acc2[1][j]);   // m = ty*4+2, +3
        const size_t base = (size_t)n * MB + m0 + ty * 4;
        if (MODE == 0) {
            float4 o;
            o.x = v[0] + bj; o.y = v[1] + bj; o.z = v[2] + bj; o.w = v[3] + bj;
            *reinterpret_cast<float4*>(outp + base) = o;
        } else {
            float4 mm4 = *reinterpret_cast<const float4*>(mem + base);
            float mmv[4] = { mm4.x, mm4.y, mm4.z, mm4.w };
            float sv[4];
#pragma unroll
            for (int h = 0; h < 4; h++) {
                float val = v[h] + bj;
                float mm = BETA * mmv[h] + val;
                float s = (mm > 1.0f) ? 1.0f : 0.0f;
                mmv[h] = mm - s;
                sv[h] = s;
            }
            float4 ms; ms.x = mmv[0]; ms.y = mmv[1]; ms.z = mmv[2]; ms.w = mmv[3];
            *reinterpret_cast<float4*>(mem + base) = ms;
            if (MODE == 1) {
                float4 sp; sp.x = sv[0]; sp.y = sv[1]; sp.z = sv[2]; sp.w = sv[3];
                *reinterpret_cast<float4*>(outp + base) = sp;
            } else {
#pragma unroll
                for (int h = 0; h < 4; h++)
                    outp[(size_t)(m0 + ty * 4 + h) * Ntot + n] += sv[h];
            }
        }
    }
}

// single-GEMM wrapper
template <int MODE>
__global__ void __launch_bounds__(256) gemmT_kernel(
    const float* __restrict__ AT, const float* __restrict__ BT,
    const float* __restrict__ bias, float* __restrict__ mem,
    float* __restrict__ outp, int K, int Ntot, int nbx)
{
    __shared__ __align__(16) float As[2 * 32 * 64];
    __shared__ __align__(16) float Bs[2 * 32 * 64];
    gemmT<MODE>(As, Bs, (blockIdx.x / nbx) * 64, (blockIdx.x % nbx) * 64,
                AT, BT, bias, mem, outp, K, Ntot);
}

// fused step: blocks [0,256) = layer-2 step t; blocks [256,320) = layer-3 step t-1
__global__ void __launch_bounds__(256) step_kernel(
    const float* __restrict__ s1t, const float* __restrict__ W2T,
    const float* __restrict__ b2, float* __restrict__ m2, float* __restrict__ s2w,
    const float* __restrict__ s2r, const float* __restrict__ W3T,
    const float* __restrict__ b3, float* __restrict__ m3, float* __restrict__ out)
{
    __shared__ __align__(16) float As[2 * 32 * 64];
    __shared__ __align__(16) float Bs[2 * 32 * 64];
    const int b = blockIdx.x;
    if (b < 256) {
        gemmT<1>(As, Bs, (b >> 5) * 64, (b & 31) * 64, s1t, W2T, b2, m2, s2w, L1N, L2N);
    } else {
        const int c = b - 256;      // 64 blocks: 8 m-tiles x 8 n-tiles
        gemmT<2>(As, Bs, (c >> 3) * 64, (c & 7) * 64, s2r, W3T, b3, m3, out, L2N, L3N);
    }
}

// ---------------- host ----------------
extern "C" void kernel_launch(void* const* d_in, const int* in_sizes, int n_in,
                              void* d_out, int out_size)
{
    const float* x  = (const float*)d_in[0];
    const float* W1 = (const float*)d_in[1];
    const float* b1 = (const float*)d_in[2];
    const float* W2 = (const float*)d_in[3];
    const float* b2 = (const float*)d_in[4];
    const float* W3 = (const float*)d_in[5];
    const float* b3 = (const float*)d_in[6];
    float* out = (float*)d_out;

    float *xT, *w1T, *w2T, *w3T, *c1T, *s1T, *s2T, *m2T, *m3T;
    cudaGetSymbolAddress((void**)&xT,  g_xT);
    cudaGetSymbolAddress((void**)&w1T, g_w1T);
    cudaGetSymbolAddress((void**)&w2T, g_w2T);
    cudaGetSymbolAddress((void**)&w3T, g_w3T);
    cudaGetSymbolAddress((void**)&c1T, g_c1T);
    cudaGetSymbolAddress((void**)&s1T, g_s1T);
    cudaGetSymbolAddress((void**)&s2T, g_s2T);
    cudaGetSymbolAddress((void**)&m2T, g_m2T);
    cudaGetSymbolAddress((void**)&m3T, g_m3T);
    float* s2buf[2] = { s2T, s2T + (size_t)L2N * MB };

    dim3 tb(32, 8);
    // one-time transposes into [K][*] layouts
    transpose_k<<<dim3(K1IN / 32, MB  / 32), tb>>>(x,  xT,  MB,  K1IN);
    transpose_k<<<dim3(K1IN / 32, L1N / 32), tb>>>(W1, w1T, L1N, K1IN);
    transpose_k<<<dim3(L1N  / 32, L2N / 32), tb>>>(W2, w2T, L2N, L1N);
    transpose_k<<<dim3(L2N  / 32, L3N / 32), tb>>>(W3, w3T, L3N, L2N);

    // zero membranes + output
    init_kernel<<<(MB * L2N + 255) / 256, 256>>>(out);

    // layer-1 current, once: c1T = (x @ W1^T + b1)^T   (grid 8x32 = 256 CTAs)
    gemmT_kernel<0><<<256, 256>>>(xT, w1T, b1, nullptr, c1T, K1IN, L1N, 32);

    // full 16-step layer-1 spike trains (coalesced, transposed layout)
    sim_layer1<<<(MB * L1N) / 256, 256>>>();

    // layer-2 step 0 (grid 256)
    gemmT_kernel<1><<<256, 256>>>(s1T, w2T, b2, m2T, s2buf[0], L1N, L2N, 32);

    // fused steps: L2(t) || L3(t-1), t = 1..15 (grid 320)
    for (int t = 1; t < TSTEPS; t++) {
        step_kernel<<<320, 256>>>(
            s1T + (size_t)t * L1N * MB, w2T, b2, m2T, s2buf[t & 1],
            s2buf[(t - 1) & 1], w3T, b3, m3T, out);
    }

    // trailing layer-3 step 15 (grid 64)
    gemmT_kernel<2><<<64, 256>>>(s2buf[1], w3T, b3, m3T, out, L2N, L3N, 8);
}

// round 12
// speedup vs baseline: 2.6976x; 1.7458x over previous
#include <cuda_runtime.h>
#include <cstdint>

#define BETA 0.95f
#define MB 512
#define L1N 2048
#define L2N 2048
#define L3N 512
#define K1IN 1024
#define TSTEPS 16

#define NM2 (L2N * MB)        // elems per t-slice of C2 / s1
#define NM3 (L3N * MB)        // elems per t-slice of C3

// ---------------- scratch (static device globals) ----------------
__device__ float g_xT [K1IN * MB];             // xT [k][m]
__device__ float g_w1T[K1IN * L1N];            // W1T[k][n]
__device__ float g_w2T[L1N * L2N];             // W2T[k][n]
__device__ float g_w3T[L2N * L3N];             // W3T[k][n]
__device__ float g_c1T[L1N * MB];              // c1T[n][m]
__device__ float g_s1 [TSTEPS * NM2];          // s1 [t][k][m]   64 MB
__device__ float g_C2 [TSTEPS * NM2];          // C2 [t][n][m]   64 MB (becomes s2 in-place)
__device__ float g_C3 [TSTEPS * NM3];          // C3 [t][n][m]   16 MB

// packed f32x2: per-lane IEEE fp32 FMA (RN) -> bit-exact vs FFMA
#define FMA2(d, a, b) \
    asm("fma.rn.f32x2 %0, %1, %2, %0;" : "+l"(d) : "l"(a), "l"(b))
#define PACK2(d, x) \
    asm("mov.b64 %0, {%1, %1};" : "=l"(d) : "f"(x))
#define UNPACK2(lo, hi, v) \
    asm("mov.b64 {%0, %1}, %2;" : "=f"(lo), "=f"(hi) : "l"(v))

// ---------------- transpose: src[R][C] -> dst[C][R] ----------------
__global__ void transpose_k(const float* __restrict__ src, float* __restrict__ dst,
                            int R, int C) {
    __shared__ float t[32][33];
    const int c0 = blockIdx.x * 32, r0 = blockIdx.y * 32;
    for (int j = threadIdx.y; j < 32; j += 8)
        t[j][threadIdx.x] = src[(size_t)(r0 + j) * C + c0 + threadIdx.x];
    __syncthreads();
    for (int j = threadIdx.y; j < 32; j += 8)
        dst[(size_t)(c0 + j) * R + r0 + threadIdx.x] = t[threadIdx.x][j];
}

// ---- layer-1: closed-form 16-step LIF on static current ----
__global__ void sim_layer1() {
    int i = blockIdx.x * blockDim.x + threadIdx.x;   // over c1T [k][m]
    float c = g_c1T[i];
    float m = 0.0f;
#pragma unroll
    for (int t = 0; t < TSTEPS; t++) {
        m = BETA * m + c;
        float s = (m > 1.0f) ? 1.0f : 0.0f;
        m -= s;
        g_s1[t * NM2 + i] = s;
    }
}

// ---------------- batched fp32x2 GEMM (bit-exact ascending-k chain) ----------------
// All A matrices are [K][512] per t-chunk; m_eff = t*512 + m. Tile 128m x 64n,
// 256 threads, per-thread 8m (4 packed pairs) x 4n, BK=32, double-buffered.
// MODE 0: out[t-chunk][n*512+m] = acc + bias[n]
// MODE 1: out[t-chunk][n*512+m] = acc               (raw; bias applied in recurrence)
template <int MODE>
__global__ void __launch_bounds__(256, 2) gemmB(
    const float* __restrict__ A, size_t chunkA,
    const float* __restrict__ BT, int Ntot,
    const float* __restrict__ bias,
    float* __restrict__ outp, size_t chunkOut,
    int K, int nbx)
{
    __shared__ __align__(16) float As[2 * 32 * 128];   // 32 KB
    __shared__ __align__(16) float Bs[2 * 32 * 64];    // 16 KB

    const int bx = blockIdx.x;
    const int m0 = (bx / nbx) * 128;     // global m_eff tile base
    const int n0 = (bx % nbx) * 64;
    const int tch = m0 >> 9;             // t-chunk (tile never straddles: 512 % 128 == 0)
    const int mloc = m0 & 511;
    const float* Ab = A + (size_t)tch * chunkA + mloc;     // k-row stride 512
    float* Ob = outp + (size_t)tch * chunkOut + mloc;

    const int tid = threadIdx.x;
    const int akk = tid >> 5;            // + i*8   (A: 32 k-rows x 128 m)
    const int amq = (tid & 31) * 4;
    const int bkk = tid >> 4;            // + i*16  (B: 32 k-rows x 64 n)
    const int bnq = (tid & 15) * 4;
    const int tx  = tid & 15;            // n: 4 cols
    const int ty  = tid >> 4;            // m: 8 rows (4 packed pairs)

    uint64_t acc2[4][4];
#pragma unroll
    for (int i = 0; i < 4; i++)
#pragma unroll
        for (int j = 0; j < 4; j++) acc2[i][j] = 0ull;

    float4 pa[4], pb[2];
    const int niter = K >> 5;

    // prologue: tile 0 -> regs -> buffer 0
#pragma unroll
    for (int i = 0; i < 4; i++)
        pa[i] = *reinterpret_cast<const float4*>(Ab + (size_t)(akk + i * 8) * 512 + amq);
#pragma unroll
    for (int i = 0; i < 2; i++)
        pb[i] = *reinterpret_cast<const float4*>(BT + (size_t)(bkk + i * 16) * Ntot + n0 + bnq);
#pragma unroll
    for (int i = 0; i < 4; i++)
        *reinterpret_cast<float4*>(As + (akk + i * 8) * 128 + amq) = pa[i];
#pragma unroll
    for (int i = 0; i < 2; i++)
        *reinterpret_cast<float4*>(Bs + (bkk + i * 16) * 64 + bnq) = pb[i];

    for (int it = 0; it < niter; it++) {
        const int b = it & 1;
        __syncthreads();

        const bool more = (it + 1 < niter);
        if (more) {
            const int k0 = (it + 1) * 32;
#pragma unroll
            for (int i = 0; i < 4; i++)
                pa[i] = *reinterpret_cast<const float4*>(Ab + (size_t)(k0 + akk + i * 8) * 512 + amq);
#pragma unroll
            for (int i = 0; i < 2; i++)
                pb[i] = *reinterpret_cast<const float4*>(BT + (size_t)(k0 + bkk + i * 16) * Ntot + n0 + bnq);
        }

        float* Abuf = As + b * (32 * 128);
        float* Bbuf = Bs + b * (32 * 64);
#pragma unroll
        for (int k = 0; k < 32; k++) {
            ulonglong2 a01 = *reinterpret_cast<const ulonglong2*>(Abuf + k * 128 + ty * 8);
            ulonglong2 a23 = *reinterpret_cast<const ulonglong2*>(Abuf + k * 128 + ty * 8 + 4);
            float4 w = *reinterpret_cast<const float4*>(Bbuf + k * 64 + tx * 4);
            uint64_t br0, br1, br2, br3;
            PACK2(br0, w.x);
            PACK2(br1, w.y);
            PACK2(br2, w.z);
            PACK2(br3, w.w);
            FMA2(acc2[0][0], a01.x, br0); FMA2(acc2[0][1], a01.x, br1);
            FMA2(acc2[0][2], a01.x, br2); FMA2(acc2[0][3], a01.x, br3);
            FMA2(acc2[1][0], a01.y, br0); FMA2(acc2[1][1], a01.y, br1);
            FMA2(acc2[1][2], a01.y, br2); FMA2(acc2[1][3], a01.y, br3);
            FMA2(acc2[2][0], a23.x, br0); FMA2(acc2[2][1], a23.x, br1);
            FMA2(acc2[2][2], a23.x, br2); FMA2(acc2[2][3], a23.x, br3);
            FMA2(acc2[3][0], a23.y, br0); FMA2(acc2[3][1], a23.y, br1);
            FMA2(acc2[3][2], a23.y, br2); FMA2(acc2[3][3], a23.y, br3);
        }

        if (more) {
            const int nb = b ^ 1;
            float* Ad = As + nb * (32 * 128);
            float* Bd = Bs + nb * (32 * 64);
#pragma unroll
            for (int i = 0; i < 4; i++)
                *reinterpret_cast<float4*>(Ad + (akk + i * 8) * 128 + amq) = pa[i];
#pragma unroll
            for (int i = 0; i < 2; i++)
                *reinterpret_cast<float4*>(Bd + (bkk + i * 16) * 64 + bnq) = pb[i];
        }
    }

    // epilogue
#pragma unroll
    for (int j = 0; j < 4; j++) {
        const int n = n0 + tx * 4 + j;
        float vv[8];
        UNPACK2(vv[0], vv[1], acc2[0][j]);
        UNPACK2(vv[2], vv[3], acc2[1][j]);
        UNPACK2(vv[4], vv[5], acc2[2][j]);
        UNPACK2(vv[6], vv[7], acc2[3][j]);
        if (MODE == 0) {
            const float bj = bias[n];
#pragma unroll
            for (int h = 0; h < 8; h++) vv[h] += bj;
        }
        float* dst = Ob + (size_t)n * 512 + ty * 8;
        float4 o0, o1;
        o0.x = vv[0]; o0.y = vv[1]; o0.z = vv[2]; o0.w = vv[3];
        o1.x = vv[4]; o1.y = vv[5]; o1.z = vv[6]; o1.w = vv[7];
        *reinterpret_cast<float4*>(dst) = o0;
        *reinterpret_cast<float4*>(dst + 4) = o1;
    }
}

// ---- layer-2 recurrence: membranes in registers, spikes written in-place over C2 ----
__global__ void rec2(const float* __restrict__ b2) {
    int i = blockIdx.x * blockDim.x + threadIdx.x;   // over [n][m], n = i>>9
    const float bj = b2[i >> 9];
    float mm = 0.0f;
#pragma unroll
    for (int t = 0; t < TSTEPS; t++) {
        float c = g_C2[t * NM2 + i];
        float v = c + bj;
        float m2 = BETA * mm + v;
        float s = (m2 > 1.0f) ? 1.0f : 0.0f;
        mm = m2 - s;
        g_C2[t * NM2 + i] = s;                       // s2 in-place
    }
}

// ---- layer-3 recurrence + output sum ----
__global__ void rec3(const float* __restrict__ b3, float* __restrict__ out) {
    int i = blockIdx.x * blockDim.x + threadIdx.x;   // over [n][m]
    const int n = i >> 9, m = i & 511;
    const float bj = b3[n];
    float mm = 0.0f, sum = 0.0f;
#pragma unroll
    for (int t = 0; t < TSTEPS; t++) {
        float c = g_C3[t * NM3 + i];
        float v = c + bj;
        float m3 = BETA * mm + v;
        float s = (m3 > 1.0f) ? 1.0f : 0.0f;
        mm = m3 - s;
        sum += s;
    }
    out[(size_t)m * L3N + n] = sum;
}

// ---------------- host ----------------
extern "C" void kernel_launch(void* const* d_in, const int* in_sizes, int n_in,
                              void* d_out, int out_size)
{
    const float* x  = (const float*)d_in[0];
    const float* W1 = (const float*)d_in[1];
    const float* b1 = (const float*)d_in[2];
    const float* W2 = (const float*)d_in[3];
    const float* b2 = (const float*)d_in[4];
    const float* W3 = (const float*)d_in[5];
    const float* b3 = (const float*)d_in[6];
    float* out = (float*)d_out;

    float *xT, *w1T, *w2T, *w3T, *c1T, *s1, *C2, *C3;
    cudaGetSymbolAddress((void**)&xT,  g_xT);
    cudaGetSymbolAddress((void**)&w1T, g_w1T);
    cudaGetSymbolAddress((void**)&w2T, g_w2T);
    cudaGetSymbolAddress((void**)&w3T, g_w3T);
    cudaGetSymbolAddress((void**)&c1T, g_c1T);
    cudaGetSymbolAddress((void**)&s1,  g_s1);
    cudaGetSymbolAddress((void**)&C2,  g_C2);
    cudaGetSymbolAddress((void**)&C3,  g_C3);

    dim3 tb(32, 8);
    transpose_k<<<dim3(K1IN / 32, MB  / 32), tb>>>(x,  xT,  MB,  K1IN);
    transpose_k<<<dim3(K1IN / 32, L1N / 32), tb>>>(W1, w1T, L1N, K1IN);
    transpose_k<<<dim3(L1N  / 32, L2N / 32), tb>>>(W2, w2T, L2N, L1N);
    transpose_k<<<dim3(L2N  / 32, L3N / 32), tb>>>(W3, w3T, L3N, L2N);

    // layer-1 current, once: c1T = (x @ W1^T + b1)^T   (grid 4*32 = 128)
    gemmB<0><<<4 * 32, 256>>>(xT, 0, w1T, L1N, b1, c1T, 0, K1IN, 32);

    // 16-step layer-1 spike trains
    sim_layer1<<<NM2 / 256, 256>>>();

    // batched layer-2 GEMM: C2[t] = s1[t] @ W2^T, M_eff = 8192  (grid 64*32 = 2048)
    gemmB<1><<<64 * 32, 256>>>(s1, (size_t)NM2, w2T, L2N, nullptr,
                               C2, (size_t)NM2, L1N, 32);

    // layer-2 membrane recurrence (registers), spikes in-place
    rec2<<<NM2 / 256, 256>>>(b2);

    // batched layer-3 GEMM: C3[t] = s2[t] @ W3^T, M_eff = 8192  (grid 64*8 = 512)
    gemmB<1><<<64 * 8, 256>>>(C2, (size_t)NM2, w3T, L3N, nullptr,
                              C3, (size_t)NM3, L2N, 8);

    // layer-3 recurrence + spike-count sum -> out
    rec3<<<NM3 / 256, 256>>>(b3, out);
}